// round 5
// baseline (speedup 1.0000x reference)
#include <cuda_runtime.h>
#include <cuda_bf16.h>
#include <cstdint>

#define D      128
#define HH     8
#define RR     6
#define BB     6
#define MAXN   50000
#define NPAD   50048              /* 391 * 128 */
#define KDIM   (RR * D)           /* 768 */
#define NOUT   (3 * D)            /* 384 */

// ---------------- scratch (static device globals; no allocation) ----------------
__device__ __align__(256) float g_S[(size_t)NPAD * KDIM];   // fp32 per-(dst,rel) sums
__device__ __align__(256) float g_Wt[(size_t)NOUT * KDIM];  // [384][768] K-major W^T, tf32-rounded
__device__ __align__(256) float g_bias[NOUT];
__device__ __align__(256) float g_QKV[(size_t)NPAD * NOUT]; // relu(S@W + b)
__device__ __align__(256) float g_wV[(size_t)MAXN * D];
__device__ __align__(256) float g_z[(size_t)MAXN * HH];

// ---------------- helpers ----------------
__device__ __forceinline__ uint32_t smem_u32(const void* p) {
    uint32_t a;
    asm("{ .reg .u64 t; cvta.to.shared.u64 t, %1; cvt.u32.u64 %0, t; }" : "=r"(a) : "l"(p));
    return a;
}
__device__ __forceinline__ void ldsm4(uint32_t addr, uint32_t* r) {
    asm volatile("ldmatrix.sync.aligned.m8n8.x4.shared.b16 {%0,%1,%2,%3}, [%4];"
                 : "=r"(r[0]), "=r"(r[1]), "=r"(r[2]), "=r"(r[3]) : "r"(addr));
}
__device__ __forceinline__ void mma_tf32(float* c, const uint32_t* a, const uint32_t* b) {
    asm volatile("mma.sync.aligned.m16n8k8.row.col.f32.tf32.tf32.f32 "
                 "{%0,%1,%2,%3}, {%4,%5,%6,%7}, {%8,%9}, {%0,%1,%2,%3};"
                 : "+f"(c[0]), "+f"(c[1]), "+f"(c[2]), "+f"(c[3])
                 : "r"(a[0]), "r"(a[1]), "r"(a[2]), "r"(a[3]), "r"(b[0]), "r"(b[1]));
}

// ---------------- zero scratch accumulators ----------------
__global__ void zero_all() {
    size_t i = (size_t)blockIdx.x * blockDim.x + threadIdx.x;
    size_t stride = (size_t)gridDim.x * blockDim.x;
    float4 z = make_float4(0.f, 0.f, 0.f, 0.f);
    size_t nS = (size_t)NPAD * KDIM / 4;
    for (size_t j = i; j < nS; j += stride) ((float4*)g_S)[j] = z;
    size_t nW = (size_t)MAXN * D / 4;
    for (size_t j = i; j < nW; j += stride) ((float4*)g_wV)[j] = z;
    size_t nZ = (size_t)MAXN * HH / 4;
    for (size_t j = i; j < nZ; j += stride) ((float4*)g_z)[j] = z;
}

// ---------------- build W^T (tf32-rounded fp32) + bias ----------------
__global__ void build_Wt(const float* __restrict__ qb, const float* __restrict__ qc, const float* __restrict__ bq,
                         const float* __restrict__ kb, const float* __restrict__ kc, const float* __restrict__ bk,
                         const float* __restrict__ vb, const float* __restrict__ vc, const float* __restrict__ bv) {
    int idx = blockIdx.x * blockDim.x + threadIdx.x;
    if (idx < NOUT)
        g_bias[idx] = (idx < D) ? bq[idx] : (idx < 2 * D) ? bk[idx - D] : bv[idx - 2 * D];
    if (idx >= NOUT * KDIM) return;
    int o = idx / KDIM;
    int k = idx - o * KDIM;
    int r = k >> 7, i2 = k & 127;
    const float* basis; const float* coef; int oo = o;
    if (o < D)          { basis = qb; coef = qc; }
    else if (o < 2 * D) { basis = kb; coef = kc; oo = o - D; }
    else                { basis = vb; coef = vc; oo = o - 2 * D; }
    float acc = 0.f;
#pragma unroll
    for (int b = 0; b < BB; b++)
        acc += coef[r * BB + b] * basis[(size_t)b * D * D + (size_t)i2 * D + oo];
    uint32_t bits;
    asm("cvt.rna.tf32.f32 %0, %1;" : "=r"(bits) : "f"(acc));
    g_Wt[idx] = __uint_as_float(bits);
}

// ---------------- scatter: S[dst, etype, :] += h[src, :] ----------------
__global__ void scatter_S(const float* __restrict__ h, const int* __restrict__ src,
                          const int* __restrict__ dst, const int* __restrict__ et, int E) {
    int warp = (blockIdx.x * blockDim.x + threadIdx.x) >> 5;
    if (warp >= E) return;
    int lane = threadIdx.x & 31;
    int s = __ldg(src + warp);
    int d0 = __ldg(dst + warp);
    int r = __ldg(et + warp);
    float4 v = __ldg((const float4*)(h + (size_t)s * D) + lane);
    float* p = g_S + ((size_t)d0 * KDIM + r * D + lane * 4);
    asm volatile("red.global.add.v4.f32 [%0], {%1,%2,%3,%4};"
                 :: "l"(p), "f"(v.x), "f"(v.y), "f"(v.z), "f"(v.w) : "memory");
}

// ---------------- tf32 mma.sync GEMM: QKV = relu(S @ W + b) ----------------
// CTA 128x128, 16 warps (warp 32x32), K-chunk 64 fp32 (256B rows, 16-chunk XOR swizzle),
// 3-stage cp.async pipeline. A raw fp32 (HW tf32 truncation), B pre-rounded rna.
#define KCH        64
#define NCHUNK     (KDIM / KCH)           /* 12 */
#define TILEB      32768                   /* 128 rows x 256B */
#define STAGEB     (2 * TILEB)             /* A + B */
#define NSTAGE     3
#define SMEM_TOTAL (NSTAGE * STAGEB)       /* 196608 */

__device__ __forceinline__ void load_tile_f32(uint32_t sdst, const float* __restrict__ g,
                                              int k0, int t) {
    // 128 rows x 256B, 16B granules: 2048 units, 4 per thread (512 threads)
#pragma unroll
    for (int i = 0; i < 4; i++) {
        int u = i * 512 + t;
        int row = u >> 4, c = u & 15;
        uint32_t off = (uint32_t)(row * 256 + ((c ^ (row & 15)) * 16));
        const void* src = g + (size_t)row * KDIM + k0 + c * 4;
        asm volatile("cp.async.cg.shared.global [%0], [%1], 16;"
                     :: "r"(sdst + off), "l"(src) : "memory");
    }
}

__global__ void __launch_bounds__(512, 1) gemm_qkv_tf32() {
    extern __shared__ char smem[];
    uint32_t sbase = smem_u32(smem);
    int t = threadIdx.x;
    int l = t & 31;
    int w = t >> 5;           // 0..15
    int wm = w & 3;           // M warp 0..3 (32 rows)
    int wn = w >> 2;          // N warp 0..3 (32 cols)
    int bm = blockIdx.y * 128;
    int bn = blockIdx.x * 128;

    const float* A = g_S + (size_t)bm * KDIM;
    const float* B = g_Wt + (size_t)bn * KDIM;

    // ldmatrix lane decomposition (constant per thread)
    int qlow = ((l >> 3) & 1) * 8 + (l & 7);  // row offset within 16-row tile
    int qhi  = l >> 4;                        // chunk offset (0/1)

    float acc[2][4][4];
#pragma unroll
    for (int i = 0; i < 2; i++)
#pragma unroll
        for (int j = 0; j < 4; j++)
#pragma unroll
            for (int k = 0; k < 4; k++) acc[i][j][k] = 0.f;

#pragma unroll
    for (int c = 0; c < NSTAGE; c++) {
        uint32_t sb = sbase + c * STAGEB;
        load_tile_f32(sb,         A, c * KCH, t);
        load_tile_f32(sb + TILEB, B, c * KCH, t);
        asm volatile("cp.async.commit_group;" ::: "memory");
    }

#pragma unroll 1
    for (int c = 0; c < NCHUNK; c++) {
        if (c < NCHUNK - 2)       asm volatile("cp.async.wait_group 2;" ::: "memory");
        else if (c == NCHUNK - 2) asm volatile("cp.async.wait_group 1;" ::: "memory");
        else                      asm volatile("cp.async.wait_group 0;" ::: "memory");
        __syncthreads();

        uint32_t sb = sbase + (c % NSTAGE) * STAGEB;
        uint32_t stA = sb;
        uint32_t stB = sb + TILEB;

#pragma unroll
        for (int ks = 0; ks < 8; ks++) {
            uint32_t af[2][4], bf[4][2];
            int sw = ((ks * 2 + qhi) ^ qlow) * 16;
#pragma unroll
            for (int mt = 0; mt < 2; mt++) {
                int row = wm * 32 + mt * 16 + qlow;
                ldsm4(stA + row * 256 + sw, af[mt]);
            }
#pragma unroll
            for (int np = 0; np < 2; np++) {
                int row = wn * 32 + np * 16 + qlow;
                uint32_t r[4];
                ldsm4(stB + row * 256 + sw, r);
                bf[np * 2][0] = r[0];     bf[np * 2][1] = r[2];
                bf[np * 2 + 1][0] = r[1]; bf[np * 2 + 1][1] = r[3];
            }
#pragma unroll
            for (int mt = 0; mt < 2; mt++)
#pragma unroll
                for (int nt = 0; nt < 4; nt++)
                    mma_tf32(acc[mt][nt], af[mt], bf[nt]);
        }
        __syncthreads();
        if (c + NSTAGE < NCHUNK) {
            int cn = c + NSTAGE;
            load_tile_f32(sb,         A, cn * KCH, t);
            load_tile_f32(sb + TILEB, B, cn * KCH, t);
            asm volatile("cp.async.commit_group;" ::: "memory");
        }
    }

    // epilogue: bias + relu (rows padded to NPAD, no bounds checks)
#pragma unroll
    for (int mt = 0; mt < 2; mt++) {
        int r0 = bm + wm * 32 + mt * 16 + (l >> 2);
#pragma unroll
        for (int nt = 0; nt < 4; nt++) {
            int col = bn + wn * 32 + nt * 8 + 2 * (l & 3);
            float2 bb = *(const float2*)(g_bias + col);
            float2 o0, o1;
            o0.x = fmaxf(acc[mt][nt][0] + bb.x, 0.f);
            o0.y = fmaxf(acc[mt][nt][1] + bb.y, 0.f);
            o1.x = fmaxf(acc[mt][nt][2] + bb.x, 0.f);
            o1.y = fmaxf(acc[mt][nt][3] + bb.y, 0.f);
            *(float2*)(g_QKV + (size_t)r0 * NOUT + col) = o0;
            *(float2*)(g_QKV + (size_t)(r0 + 8) * NOUT + col) = o1;
        }
    }
}

// ---------------- attention: warp per edge ----------------
__global__ void attn_kernel(const int* __restrict__ src, const int* __restrict__ dst, int E) {
    int warp = (blockIdx.x * blockDim.x + threadIdx.x) >> 5;
    if (warp >= E) return;
    int lane = threadIdx.x & 31;
    int s = __ldg(src + warp);
    int d0 = __ldg(dst + warp);
    const float4* q4 = (const float4*)(g_QKV + (size_t)d0 * NOUT);
    const float4* k4 = (const float4*)(g_QKV + (size_t)s * NOUT + D);
    const float4* v4 = (const float4*)(g_QKV + (size_t)s * NOUT + 2 * D);
    float4 q = q4[lane], k = k4[lane], v = v4[lane];
    float p = q.x * k.x + q.y * k.y + q.z * k.z + q.w * k.w;
    p += __shfl_xor_sync(0xffffffffu, p, 1);
    p += __shfl_xor_sync(0xffffffffu, p, 2);
    float sc = fminf(fmaxf(p * 0.25f, -10.0f), 10.0f);
    float w = __expf(sc);
    float* pw = g_wV + ((size_t)d0 * D + lane * 4);
    asm volatile("red.global.add.v4.f32 [%0], {%1,%2,%3,%4};"
                 :: "l"(pw), "f"(v.x * w), "f"(v.y * w), "f"(v.z * w), "f"(v.w * w) : "memory");
    if ((lane & 3) == 0)
        atomicAdd(g_z + (size_t)d0 * HH + (lane >> 2), w);
}

// ---------------- finalize ----------------
__global__ void finalize(float* __restrict__ out, int N) {
    int idx = blockIdx.x * blockDim.x + threadIdx.x;
    if (idx >= N * D) return;
    int n = idx >> 7;
    int c = idx & 127;
    out[idx] = g_wV[idx] / (g_z[n * HH + (c >> 4)] + 1e-6f);
}

extern "C" void kernel_launch(void* const* d_in, const int* in_sizes, int n_in,
                              void* d_out, int out_size) {
    const float* h   = (const float*)d_in[0];
    const int*   src = (const int*)d_in[1];
    const int*   dst = (const int*)d_in[2];
    const int*   et  = (const int*)d_in[3];
    const float* Wq_basis = (const float*)d_in[4];
    const float* Wq_coef  = (const float*)d_in[5];
    const float* bq       = (const float*)d_in[6];
    const float* Wk_basis = (const float*)d_in[7];
    const float* Wk_coef  = (const float*)d_in[8];
    const float* bk       = (const float*)d_in[9];
    const float* Wv_basis = (const float*)d_in[10];
    const float* Wv_coef  = (const float*)d_in[11];
    const float* bv       = (const float*)d_in[12];
    float* out = (float*)d_out;

    int N = in_sizes[0] / D;   // 50000
    int E = in_sizes[1];       // 500000

    static bool attr_set = false;
    if (!attr_set) {
        cudaFuncSetAttribute(gemm_qkv_tf32, cudaFuncAttributeMaxDynamicSharedMemorySize, SMEM_TOTAL);
        attr_set = true;
    }

    zero_all<<<2048, 256>>>();
    build_Wt<<<(NOUT * KDIM + 255) / 256, 256>>>(Wq_basis, Wq_coef, bq,
                                                 Wk_basis, Wk_coef, bk,
                                                 Wv_basis, Wv_coef, bv);
    {
        long long threads = (long long)E * 32;
        int blocks = (int)((threads + 255) / 256);
        scatter_S<<<blocks, 256>>>(h, src, dst, et, E);
    }
    {
        dim3 gg(NOUT / 128, NPAD / 128);
        gemm_qkv_tf32<<<gg, 512, SMEM_TOTAL>>>();
    }
    {
        long long threads = (long long)E * 32;
        int blocks = (int)((threads + 255) / 256);
        attn_kernel<<<blocks, 256>>>(src, dst, E);
    }
    finalize<<<(N * D + 255) / 256, 256>>>(out, N);
}

// round 6
// speedup vs baseline: 1.0490x; 1.0490x over previous
#include <cuda_runtime.h>
#include <cuda_bf16.h>
#include <cstdint>

#define D      128
#define HH     8
#define RR     6
#define BB     6
#define MAXN   50000
#define NPAD   50048              /* 391 * 128 */
#define KDIM   (RR * D)           /* 768 */
#define NOUT   (3 * D)            /* 384 */
#define MAXE   500000

// ---------------- scratch (static device globals; no allocation) ----------------
__device__ __align__(256) float g_S[(size_t)NPAD * KDIM];   // fp32 per-(dst,rel) sums; rows >= MAXN stay 0
__device__ __align__(256) float g_Wt[(size_t)NOUT * KDIM];  // [384][768] K-major W^T, tf32-rounded
__device__ __align__(256) float g_bias[NOUT];
__device__ __align__(256) float g_QKV[(size_t)NPAD * NOUT]; // relu(S@W + b)
__device__ int g_deg[MAXN];
__device__ int g_rowptr[MAXN + 1];
__device__ int g_cursor[MAXN];
__device__ int g_epack[MAXE];                               // (src<<3)|rel, sorted by dst

// ---------------- helpers ----------------
__device__ __forceinline__ uint32_t smem_u32(const void* p) {
    uint32_t a;
    asm("{ .reg .u64 t; cvta.to.shared.u64 t, %1; cvt.u32.u64 %0, t; }" : "=r"(a) : "l"(p));
    return a;
}
__device__ __forceinline__ void ldsm4(uint32_t addr, uint32_t* r) {
    asm volatile("ldmatrix.sync.aligned.m8n8.x4.shared.b16 {%0,%1,%2,%3}, [%4];"
                 : "=r"(r[0]), "=r"(r[1]), "=r"(r[2]), "=r"(r[3]) : "r"(addr));
}
__device__ __forceinline__ void mma_tf32(float* c, const uint32_t* a, const uint32_t* b) {
    asm volatile("mma.sync.aligned.m16n8k8.row.col.f32.tf32.tf32.f32 "
                 "{%0,%1,%2,%3}, {%4,%5,%6,%7}, {%8,%9}, {%0,%1,%2,%3};"
                 : "+f"(c[0]), "+f"(c[1]), "+f"(c[2]), "+f"(c[3])
                 : "r"(a[0]), "r"(a[1]), "r"(a[2]), "r"(a[3]), "r"(b[0]), "r"(b[1]));
}

// ---------------- CSR build ----------------
__global__ void zero_deg() {
    int i = blockIdx.x * blockDim.x + threadIdx.x;
    if (i < MAXN) g_deg[i] = 0;
}
__global__ void hist_deg(const int* __restrict__ dst, int E) {
    int i = blockIdx.x * blockDim.x + threadIdx.x;
    if (i < E) atomicAdd(&g_deg[dst[i]], 1);
}
#define SCAN_T 1024
#define CHUNK  49   /* 1024*49 = 50176 >= MAXN */
__global__ void __launch_bounds__(SCAN_T) scan_deg() {
    __shared__ int sums[SCAN_T];
    int t = threadIdx.x;
    int base = t * CHUNK;
    int s = 0;
#pragma unroll 1
    for (int i = 0; i < CHUNK; i++) {
        int idx = base + i;
        if (idx < MAXN) s += g_deg[idx];
    }
    sums[t] = s;
    __syncthreads();
    for (int off = 1; off < SCAN_T; off <<= 1) {
        int v = (t >= off) ? sums[t - off] : 0;
        __syncthreads();
        if (t >= off) sums[t] += v;
        __syncthreads();
    }
    int excl = (t == 0) ? 0 : sums[t - 1];
#pragma unroll 1
    for (int i = 0; i < CHUNK; i++) {
        int idx = base + i;
        if (idx < MAXN) {
            g_rowptr[idx] = excl;
            g_cursor[idx] = excl;
            excl += g_deg[idx];
        }
    }
    if (t == SCAN_T - 1) g_rowptr[MAXN] = excl;
}
__global__ void place_edges(const int* __restrict__ src, const int* __restrict__ dst,
                            const int* __restrict__ et, int E) {
    int i = blockIdx.x * blockDim.x + threadIdx.x;
    if (i >= E) return;
    int pos = atomicAdd(&g_cursor[dst[i]], 1);
    g_epack[pos] = (src[i] << 3) | et[i];
}

// ---------------- build W^T (tf32-rounded fp32) + bias ----------------
__global__ void build_Wt(const float* __restrict__ qb, const float* __restrict__ qc, const float* __restrict__ bq,
                         const float* __restrict__ kb, const float* __restrict__ kc, const float* __restrict__ bk,
                         const float* __restrict__ vb, const float* __restrict__ vc, const float* __restrict__ bv) {
    int idx = blockIdx.x * blockDim.x + threadIdx.x;
    if (idx < NOUT)
        g_bias[idx] = (idx < D) ? bq[idx] : (idx < 2 * D) ? bk[idx - D] : bv[idx - 2 * D];
    if (idx >= NOUT * KDIM) return;
    int o = idx / KDIM;
    int k = idx - o * KDIM;
    int r = k >> 7, i2 = k & 127;
    const float* basis; const float* coef; int oo = o;
    if (o < D)          { basis = qb; coef = qc; }
    else if (o < 2 * D) { basis = kb; coef = kc; oo = o - D; }
    else                { basis = vb; coef = vc; oo = o - 2 * D; }
    float acc = 0.f;
#pragma unroll
    for (int b = 0; b < BB; b++)
        acc += coef[r * BB + b] * basis[(size_t)b * D * D + (size_t)i2 * D + oo];
    uint32_t bits;
    asm("cvt.rna.tf32.f32 %0, %1;" : "=r"(bits) : "f"(acc));
    g_Wt[idx] = __uint_as_float(bits);
}

// ---------------- scatter via CSR: warp per dst, register accum, plain stores ----------------
__global__ void scatter_csr(const float* __restrict__ h) {
    int d = blockIdx.x * (blockDim.x >> 5) + (threadIdx.x >> 5);
    if (d >= MAXN) return;
    int lane = threadIdx.x & 31;
    int e0 = __ldg(g_rowptr + d), e1 = __ldg(g_rowptr + d + 1);
    float4 a0 = {0,0,0,0}, a1 = {0,0,0,0}, a2 = {0,0,0,0},
           a3 = {0,0,0,0}, a4 = {0,0,0,0}, a5 = {0,0,0,0};
#pragma unroll 1
    for (int e = e0; e < e1; e++) {
        int pk = __ldg(g_epack + e);
        int src = pk >> 3, rel = pk & 7;
        float4 v = __ldg((const float4*)(h + (size_t)src * D) + lane);
        switch (rel) {
            case 0: a0.x += v.x; a0.y += v.y; a0.z += v.z; a0.w += v.w; break;
            case 1: a1.x += v.x; a1.y += v.y; a1.z += v.z; a1.w += v.w; break;
            case 2: a2.x += v.x; a2.y += v.y; a2.z += v.z; a2.w += v.w; break;
            case 3: a3.x += v.x; a3.y += v.y; a3.z += v.z; a3.w += v.w; break;
            case 4: a4.x += v.x; a4.y += v.y; a4.z += v.z; a4.w += v.w; break;
            default: a5.x += v.x; a5.y += v.y; a5.z += v.z; a5.w += v.w; break;
        }
    }
    float4* srow = (float4*)(g_S + (size_t)d * KDIM);
    srow[0 * 32 + lane] = a0;
    srow[1 * 32 + lane] = a1;
    srow[2 * 32 + lane] = a2;
    srow[3 * 32 + lane] = a3;
    srow[4 * 32 + lane] = a4;
    srow[5 * 32 + lane] = a5;
}

// ---------------- tf32 mma.sync GEMM: QKV = relu(S @ W + b) ----------------
#define KCH        64
#define NCHUNK     (KDIM / KCH)           /* 12 */
#define TILEB      32768                   /* 128 rows x 256B */
#define STAGEB     (2 * TILEB)             /* A + B */
#define NSTAGE     3
#define SMEM_TOTAL (NSTAGE * STAGEB)       /* 196608 */

__device__ __forceinline__ void load_tile_f32(uint32_t sdst, const float* __restrict__ g,
                                              int k0, int t) {
#pragma unroll
    for (int i = 0; i < 4; i++) {
        int u = i * 512 + t;
        int row = u >> 4, c = u & 15;
        uint32_t off = (uint32_t)(row * 256 + ((c ^ (row & 15)) * 16));
        const void* src = g + (size_t)row * KDIM + k0 + c * 4;
        asm volatile("cp.async.cg.shared.global [%0], [%1], 16;"
                     :: "r"(sdst + off), "l"(src) : "memory");
    }
}

__global__ void __launch_bounds__(512, 1) gemm_qkv_tf32() {
    extern __shared__ char smem[];
    uint32_t sbase = smem_u32(smem);
    int t = threadIdx.x;
    int l = t & 31;
    int w = t >> 5;
    int wm = w & 3;
    int wn = w >> 2;
    int bm = blockIdx.y * 128;
    int bn = blockIdx.x * 128;

    const float* A = g_S + (size_t)bm * KDIM;
    const float* B = g_Wt + (size_t)bn * KDIM;

    int qlow = ((l >> 3) & 1) * 8 + (l & 7);
    int qhi  = l >> 4;

    float acc[2][4][4];
#pragma unroll
    for (int i = 0; i < 2; i++)
#pragma unroll
        for (int j = 0; j < 4; j++)
#pragma unroll
            for (int k = 0; k < 4; k++) acc[i][j][k] = 0.f;

#pragma unroll
    for (int c = 0; c < NSTAGE; c++) {
        uint32_t sb = sbase + c * STAGEB;
        load_tile_f32(sb,         A, c * KCH, t);
        load_tile_f32(sb + TILEB, B, c * KCH, t);
        asm volatile("cp.async.commit_group;" ::: "memory");
    }

#pragma unroll 1
    for (int c = 0; c < NCHUNK; c++) {
        if (c < NCHUNK - 2)       asm volatile("cp.async.wait_group 2;" ::: "memory");
        else if (c == NCHUNK - 2) asm volatile("cp.async.wait_group 1;" ::: "memory");
        else                      asm volatile("cp.async.wait_group 0;" ::: "memory");
        __syncthreads();

        uint32_t sb = sbase + (c % NSTAGE) * STAGEB;
        uint32_t stA = sb;
        uint32_t stB = sb + TILEB;

#pragma unroll
        for (int ks = 0; ks < 8; ks++) {
            uint32_t af[2][4], bf[4][2];
            int sw = ((ks * 2 + qhi) ^ qlow) * 16;
#pragma unroll
            for (int mt = 0; mt < 2; mt++) {
                int row = wm * 32 + mt * 16 + qlow;
                ldsm4(stA + row * 256 + sw, af[mt]);
            }
#pragma unroll
            for (int np = 0; np < 2; np++) {
                int row = wn * 32 + np * 16 + qlow;
                uint32_t r[4];
                ldsm4(stB + row * 256 + sw, r);
                bf[np * 2][0] = r[0];     bf[np * 2][1] = r[2];
                bf[np * 2 + 1][0] = r[1]; bf[np * 2 + 1][1] = r[3];
            }
#pragma unroll
            for (int mt = 0; mt < 2; mt++)
#pragma unroll
                for (int nt = 0; nt < 4; nt++)
                    mma_tf32(acc[mt][nt], af[mt], bf[nt]);
        }
        __syncthreads();
        if (c + NSTAGE < NCHUNK) {
            int cn = c + NSTAGE;
            load_tile_f32(sb,         A, cn * KCH, t);
            load_tile_f32(sb + TILEB, B, cn * KCH, t);
            asm volatile("cp.async.commit_group;" ::: "memory");
        }
    }

#pragma unroll
    for (int mt = 0; mt < 2; mt++) {
        int r0 = bm + wm * 32 + mt * 16 + (l >> 2);
#pragma unroll
        for (int nt = 0; nt < 4; nt++) {
            int col = bn + wn * 32 + nt * 8 + 2 * (l & 3);
            float2 bb = *(const float2*)(g_bias + col);
            float2 o0, o1;
            o0.x = fmaxf(acc[mt][nt][0] + bb.x, 0.f);
            o0.y = fmaxf(acc[mt][nt][1] + bb.y, 0.f);
            o1.x = fmaxf(acc[mt][nt][2] + bb.x, 0.f);
            o1.y = fmaxf(acc[mt][nt][3] + bb.y, 0.f);
            *(float2*)(g_QKV + (size_t)r0 * NOUT + col) = o0;
            *(float2*)(g_QKV + (size_t)(r0 + 8) * NOUT + col) = o1;
        }
    }
}

// ---------------- attention via CSR: warp per dst, no atomics, direct output ----------------
__global__ void attn_csr(float* __restrict__ out) {
    int d = blockIdx.x * (blockDim.x >> 5) + (threadIdx.x >> 5);
    if (d >= MAXN) return;
    int lane = threadIdx.x & 31;
    int e0 = __ldg(g_rowptr + d), e1 = __ldg(g_rowptr + d + 1);
    float4 q = __ldg((const float4*)(g_QKV + (size_t)d * NOUT) + lane);
    float4 wv = {0, 0, 0, 0};
    float z = 0.f;
#pragma unroll 1
    for (int e = e0; e < e1; e++) {
        int src = __ldg(g_epack + e) >> 3;
        float4 k = __ldg((const float4*)(g_QKV + (size_t)src * NOUT + D) + lane);
        float4 v = __ldg((const float4*)(g_QKV + (size_t)src * NOUT + 2 * D) + lane);
        float p = q.x * k.x + q.y * k.y + q.z * k.z + q.w * k.w;
        p += __shfl_xor_sync(0xffffffffu, p, 1);
        p += __shfl_xor_sync(0xffffffffu, p, 2);
        float w = __expf(fminf(fmaxf(p * 0.25f, -10.f), 10.f));
        wv.x += v.x * w; wv.y += v.y * w; wv.z += v.z * w; wv.w += v.w * w;
        z += w;
    }
    float inv = 1.f / (z + 1e-6f);
    float4 o = {wv.x * inv, wv.y * inv, wv.z * inv, wv.w * inv};
    *((float4*)(out + (size_t)d * D) + lane) = o;
}

extern "C" void kernel_launch(void* const* d_in, const int* in_sizes, int n_in,
                              void* d_out, int out_size) {
    const float* h   = (const float*)d_in[0];
    const int*   src = (const int*)d_in[1];
    const int*   dst = (const int*)d_in[2];
    const int*   et  = (const int*)d_in[3];
    const float* Wq_basis = (const float*)d_in[4];
    const float* Wq_coef  = (const float*)d_in[5];
    const float* bq       = (const float*)d_in[6];
    const float* Wk_basis = (const float*)d_in[7];
    const float* Wk_coef  = (const float*)d_in[8];
    const float* bk       = (const float*)d_in[9];
    const float* Wv_basis = (const float*)d_in[10];
    const float* Wv_coef  = (const float*)d_in[11];
    const float* bv       = (const float*)d_in[12];
    float* out = (float*)d_out;

    int E = in_sizes[1];       // 500000

    static bool attr_set = false;
    if (!attr_set) {
        cudaFuncSetAttribute(gemm_qkv_tf32, cudaFuncAttributeMaxDynamicSharedMemorySize, SMEM_TOTAL);
        attr_set = true;
    }

    // CSR build
    zero_deg<<<(MAXN + 255) / 256, 256>>>();
    hist_deg<<<(E + 255) / 256, 256>>>(dst, E);
    scan_deg<<<1, SCAN_T>>>();
    place_edges<<<(E + 255) / 256, 256>>>(src, dst, et, E);

    build_Wt<<<(NOUT * KDIM + 255) / 256, 256>>>(Wq_basis, Wq_coef, bq,
                                                 Wk_basis, Wk_coef, bk,
                                                 Wv_basis, Wv_coef, bv);

    scatter_csr<<<(MAXN * 32 + 255) / 256, 256>>>(h);

    {
        dim3 gg(NOUT / 128, NPAD / 128);
        gemm_qkv_tf32<<<gg, 512, SMEM_TOTAL>>>();
    }

    attn_csr<<<(MAXN * 32 + 255) / 256, 256>>>(out);
}

// round 7
// speedup vs baseline: 1.0724x; 1.0223x over previous
#include <cuda_runtime.h>
#include <cuda_bf16.h>
#include <cstdint>

#define D      128
#define HH     8
#define RR     6
#define BB     6
#define MAXN   50000
#define NPAD   50048              /* 782 * 64 */
#define KDIM   (RR * D)           /* 768 */
#define NOUT   (3 * D)            /* 384 */
#define MAXE   500000

// ---------------- scratch (static device globals; no allocation) ----------------
__device__ __align__(256) float g_S[(size_t)NPAD * KDIM];   // fp32 per-(dst,rel) sums; rows >= MAXN stay 0
__device__ __align__(256) float g_Wt[(size_t)NOUT * KDIM];  // [384][768] K-major W^T, tf32-rounded
__device__ __align__(256) float g_bias[NOUT];
__device__ __align__(256) float g_QKV[(size_t)NPAD * NOUT]; // relu(S@W + b)
__device__ int g_deg[MAXN];
__device__ int g_rowptr[MAXN + 1];
__device__ int g_cursor[MAXN];
__device__ int g_epack[MAXE];                               // (src<<3)|rel, sorted by dst

// ---------------- helpers ----------------
__device__ __forceinline__ uint32_t smem_u32(const void* p) {
    uint32_t a;
    asm("{ .reg .u64 t; cvta.to.shared.u64 t, %1; cvt.u32.u64 %0, t; }" : "=r"(a) : "l"(p));
    return a;
}
__device__ __forceinline__ void ldsm4(uint32_t addr, uint32_t* r) {
    asm volatile("ldmatrix.sync.aligned.m8n8.x4.shared.b16 {%0,%1,%2,%3}, [%4];"
                 : "=r"(r[0]), "=r"(r[1]), "=r"(r[2]), "=r"(r[3]) : "r"(addr));
}
__device__ __forceinline__ void mma_tf32(float* c, const uint32_t* a, const uint32_t* b) {
    asm volatile("mma.sync.aligned.m16n8k8.row.col.f32.tf32.tf32.f32 "
                 "{%0,%1,%2,%3}, {%4,%5,%6,%7}, {%8,%9}, {%0,%1,%2,%3};"
                 : "+f"(c[0]), "+f"(c[1]), "+f"(c[2]), "+f"(c[3])
                 : "r"(a[0]), "r"(a[1]), "r"(a[2]), "r"(a[3]), "r"(b[0]), "r"(b[1]));
}

// ---------------- CSR build ----------------
__global__ void zero_deg() {
    int i = blockIdx.x * blockDim.x + threadIdx.x;
    if (i < MAXN) g_deg[i] = 0;
}
__global__ void hist_deg(const int* __restrict__ dst, int E) {
    int i = blockIdx.x * blockDim.x + threadIdx.x;
    if (i < E) atomicAdd(&g_deg[dst[i]], 1);
}
#define SCAN_T 1024
#define CHUNK  49   /* 1024*49 = 50176 >= MAXN */
__global__ void __launch_bounds__(SCAN_T) scan_deg() {
    __shared__ int sums[SCAN_T];
    int t = threadIdx.x;
    int base = t * CHUNK;
    int s = 0;
#pragma unroll 1
    for (int i = 0; i < CHUNK; i++) {
        int idx = base + i;
        if (idx < MAXN) s += g_deg[idx];
    }
    sums[t] = s;
    __syncthreads();
    for (int off = 1; off < SCAN_T; off <<= 1) {
        int v = (t >= off) ? sums[t - off] : 0;
        __syncthreads();
        if (t >= off) sums[t] += v;
        __syncthreads();
    }
    int excl = (t == 0) ? 0 : sums[t - 1];
#pragma unroll 1
    for (int i = 0; i < CHUNK; i++) {
        int idx = base + i;
        if (idx < MAXN) {
            g_rowptr[idx] = excl;
            g_cursor[idx] = excl;
            excl += g_deg[idx];
        }
    }
    if (t == SCAN_T - 1) g_rowptr[MAXN] = excl;
}
__global__ void place_edges(const int* __restrict__ src, const int* __restrict__ dst,
                            const int* __restrict__ et, int E) {
    int i = blockIdx.x * blockDim.x + threadIdx.x;
    if (i >= E) return;
    int pos = atomicAdd(&g_cursor[dst[i]], 1);
    g_epack[pos] = (src[i] << 3) | et[i];
}

// ---------------- build W^T (tf32-rounded fp32) + bias ----------------
__global__ void build_Wt(const float* __restrict__ qb, const float* __restrict__ qc, const float* __restrict__ bq,
                         const float* __restrict__ kb, const float* __restrict__ kc, const float* __restrict__ bk,
                         const float* __restrict__ vb, const float* __restrict__ vc, const float* __restrict__ bv) {
    int idx = blockIdx.x * blockDim.x + threadIdx.x;
    if (idx < NOUT)
        g_bias[idx] = (idx < D) ? bq[idx] : (idx < 2 * D) ? bk[idx - D] : bv[idx - 2 * D];
    if (idx >= NOUT * KDIM) return;
    int o = idx / KDIM;
    int k = idx - o * KDIM;
    int r = k >> 7, i2 = k & 127;
    const float* basis; const float* coef; int oo = o;
    if (o < D)          { basis = qb; coef = qc; }
    else if (o < 2 * D) { basis = kb; coef = kc; oo = o - D; }
    else                { basis = vb; coef = vc; oo = o - 2 * D; }
    float acc = 0.f;
#pragma unroll
    for (int b = 0; b < BB; b++)
        acc += coef[r * BB + b] * basis[(size_t)b * D * D + (size_t)i2 * D + oo];
    uint32_t bits;
    asm("cvt.rna.tf32.f32 %0, %1;" : "=r"(bits) : "f"(acc));
    g_Wt[idx] = __uint_as_float(bits);
}

// ---------------- scatter via CSR: warp per dst, register accum, plain stores ----------------
__global__ void scatter_csr(const float* __restrict__ h) {
    int d = blockIdx.x * (blockDim.x >> 5) + (threadIdx.x >> 5);
    if (d >= MAXN) return;
    int lane = threadIdx.x & 31;
    int e0 = __ldg(g_rowptr + d), e1 = __ldg(g_rowptr + d + 1);
    float4 a0 = {0,0,0,0}, a1 = {0,0,0,0}, a2 = {0,0,0,0},
           a3 = {0,0,0,0}, a4 = {0,0,0,0}, a5 = {0,0,0,0};
#pragma unroll 1
    for (int e = e0; e < e1; e++) {
        int pk = __ldg(g_epack + e);
        int src = pk >> 3, rel = pk & 7;
        float4 v = __ldg((const float4*)(h + (size_t)src * D) + lane);
        switch (rel) {
            case 0: a0.x += v.x; a0.y += v.y; a0.z += v.z; a0.w += v.w; break;
            case 1: a1.x += v.x; a1.y += v.y; a1.z += v.z; a1.w += v.w; break;
            case 2: a2.x += v.x; a2.y += v.y; a2.z += v.z; a2.w += v.w; break;
            case 3: a3.x += v.x; a3.y += v.y; a3.z += v.z; a3.w += v.w; break;
            case 4: a4.x += v.x; a4.y += v.y; a4.z += v.z; a4.w += v.w; break;
            default: a5.x += v.x; a5.y += v.y; a5.z += v.z; a5.w += v.w; break;
        }
    }
    float4* srow = (float4*)(g_S + (size_t)d * KDIM);
    srow[0 * 32 + lane] = a0;
    srow[1 * 32 + lane] = a1;
    srow[2 * 32 + lane] = a2;
    srow[3 * 32 + lane] = a3;
    srow[4 * 32 + lane] = a4;
    srow[5 * 32 + lane] = a5;
}

// ---------------- tf32 mma.sync GEMM: QKV = relu(S @ W + b) ----------------
// CTA 64(M) x 128(N), 8 warps (2M x 4N of 32x32), K-chunk 64, 2-stage cp.async,
// 96 KB smem -> 2 CTAs/SM so barrier gaps of one CTA are filled by the other.
#define KCH        64
#define NCHUNK     (KDIM / KCH)           /* 12 */
#define ATILEB     (64 * 256)              /* 16384 */
#define BTILEB     (128 * 256)             /* 32768 */
#define STAGEB     (ATILEB + BTILEB)       /* 49152 */
#define NSTAGE     2
#define SMEM_TOTAL (NSTAGE * STAGEB)       /* 98304 */

__device__ __forceinline__ void load_tileA(uint32_t sdst, const float* __restrict__ g,
                                           int k0, int t) {
    // 64 rows x 256B = 1024 granules, 4 per thread
#pragma unroll
    for (int i = 0; i < 4; i++) {
        int u = i * 256 + t;
        int row = u >> 4, c = u & 15;
        uint32_t off = (uint32_t)(row * 256 + ((c ^ (row & 15)) * 16));
        const void* src = g + (size_t)row * KDIM + k0 + c * 4;
        asm volatile("cp.async.cg.shared.global [%0], [%1], 16;"
                     :: "r"(sdst + off), "l"(src) : "memory");
    }
}
__device__ __forceinline__ void load_tileB(uint32_t sdst, const float* __restrict__ g,
                                           int k0, int t) {
    // 128 rows x 256B = 2048 granules, 8 per thread
#pragma unroll
    for (int i = 0; i < 8; i++) {
        int u = i * 256 + t;
        int row = u >> 4, c = u & 15;
        uint32_t off = (uint32_t)(row * 256 + ((c ^ (row & 15)) * 16));
        const void* src = g + (size_t)row * KDIM + k0 + c * 4;
        asm volatile("cp.async.cg.shared.global [%0], [%1], 16;"
                     :: "r"(sdst + off), "l"(src) : "memory");
    }
}

__global__ void __launch_bounds__(256, 2) gemm_qkv_tf32() {
    extern __shared__ char smem[];
    uint32_t sbase = smem_u32(smem);
    int t = threadIdx.x;
    int l = t & 31;
    int w = t >> 5;           // 0..7
    int wm = w & 1;           // M warp 0..1 (32 rows)
    int wn = w >> 1;          // N warp 0..3 (32 cols)
    int bm = blockIdx.y * 64;
    int bn = blockIdx.x * 128;

    const float* A = g_S + (size_t)bm * KDIM;
    const float* B = g_Wt + (size_t)bn * KDIM;

    int qlow = ((l >> 3) & 1) * 8 + (l & 7);  // row offset within 16-row tile
    int qhi  = l >> 4;                        // chunk offset (0/1)

    float acc[2][4][4];
#pragma unroll
    for (int i = 0; i < 2; i++)
#pragma unroll
        for (int j = 0; j < 4; j++)
#pragma unroll
            for (int k = 0; k < 4; k++) acc[i][j][k] = 0.f;

#pragma unroll
    for (int c = 0; c < NSTAGE; c++) {
        uint32_t sb = sbase + c * STAGEB;
        load_tileA(sb,          A, c * KCH, t);
        load_tileB(sb + ATILEB, B, c * KCH, t);
        asm volatile("cp.async.commit_group;" ::: "memory");
    }

#pragma unroll 1
    for (int c = 0; c < NCHUNK; c++) {
        if (c < NCHUNK - 1) asm volatile("cp.async.wait_group 1;" ::: "memory");
        else                asm volatile("cp.async.wait_group 0;" ::: "memory");
        __syncthreads();

        uint32_t sb = sbase + (c & 1) * STAGEB;
        uint32_t stA = sb;
        uint32_t stB = sb + ATILEB;

#pragma unroll
        for (int ks = 0; ks < 8; ks++) {
            uint32_t af[2][4], bf[4][2];
            int sw = ((ks * 2 + qhi) ^ qlow) * 16;
#pragma unroll
            for (int mt = 0; mt < 2; mt++) {
                int row = wm * 32 + mt * 16 + qlow;
                ldsm4(stA + row * 256 + sw, af[mt]);
            }
#pragma unroll
            for (int np = 0; np < 2; np++) {
                int row = wn * 32 + np * 16 + qlow;
                uint32_t r[4];
                ldsm4(stB + row * 256 + sw, r);
                bf[np * 2][0] = r[0];     bf[np * 2][1] = r[2];
                bf[np * 2 + 1][0] = r[1]; bf[np * 2 + 1][1] = r[3];
            }
#pragma unroll
            for (int mt = 0; mt < 2; mt++)
#pragma unroll
                for (int nt = 0; nt < 4; nt++)
                    mma_tf32(acc[mt][nt], af[mt], bf[nt]);
        }
        __syncthreads();
        if (c + NSTAGE < NCHUNK) {
            int cn = c + NSTAGE;
            load_tileA(sb,          A, cn * KCH, t);
            load_tileB(sb + ATILEB, B, cn * KCH, t);
            asm volatile("cp.async.commit_group;" ::: "memory");
        }
    }

    // epilogue: bias + relu (rows padded to NPAD, no bounds checks)
#pragma unroll
    for (int mt = 0; mt < 2; mt++) {
        int r0 = bm + wm * 32 + mt * 16 + (l >> 2);
#pragma unroll
        for (int nt = 0; nt < 4; nt++) {
            int col = bn + wn * 32 + nt * 8 + 2 * (l & 3);
            float2 bb = *(const float2*)(g_bias + col);
            float2 o0, o1;
            o0.x = fmaxf(acc[mt][nt][0] + bb.x, 0.f);
            o0.y = fmaxf(acc[mt][nt][1] + bb.y, 0.f);
            o1.x = fmaxf(acc[mt][nt][2] + bb.x, 0.f);
            o1.y = fmaxf(acc[mt][nt][3] + bb.y, 0.f);
            *(float2*)(g_QKV + (size_t)r0 * NOUT + col) = o0;
            *(float2*)(g_QKV + (size_t)(r0 + 8) * NOUT + col) = o1;
        }
    }
}

// ---------------- attention via CSR: warp per dst, no atomics, direct output ----------------
__global__ void attn_csr(float* __restrict__ out) {
    int d = blockIdx.x * (blockDim.x >> 5) + (threadIdx.x >> 5);
    if (d >= MAXN) return;
    int lane = threadIdx.x & 31;
    int e0 = __ldg(g_rowptr + d), e1 = __ldg(g_rowptr + d + 1);
    float4 q = __ldg((const float4*)(g_QKV + (size_t)d * NOUT) + lane);
    float4 wv = {0, 0, 0, 0};
    float z = 0.f;
#pragma unroll 1
    for (int e = e0; e < e1; e++) {
        int src = __ldg(g_epack + e) >> 3;
        float4 k = __ldg((const float4*)(g_QKV + (size_t)src * NOUT + D) + lane);
        float4 v = __ldg((const float4*)(g_QKV + (size_t)src * NOUT + 2 * D) + lane);
        float p = q.x * k.x + q.y * k.y + q.z * k.z + q.w * k.w;
        p += __shfl_xor_sync(0xffffffffu, p, 1);
        p += __shfl_xor_sync(0xffffffffu, p, 2);
        float w = __expf(fminf(fmaxf(p * 0.25f, -10.f), 10.f));
        wv.x += v.x * w; wv.y += v.y * w; wv.z += v.z * w; wv.w += v.w * w;
        z += w;
    }
    float inv = 1.f / (z + 1e-6f);
    float4 o = {wv.x * inv, wv.y * inv, wv.z * inv, wv.w * inv};
    *((float4*)(out + (size_t)d * D) + lane) = o;
}

extern "C" void kernel_launch(void* const* d_in, const int* in_sizes, int n_in,
                              void* d_out, int out_size) {
    const float* h   = (const float*)d_in[0];
    const int*   src = (const int*)d_in[1];
    const int*   dst = (const int*)d_in[2];
    const int*   et  = (const int*)d_in[3];
    const float* Wq_basis = (const float*)d_in[4];
    const float* Wq_coef  = (const float*)d_in[5];
    const float* bq       = (const float*)d_in[6];
    const float* Wk_basis = (const float*)d_in[7];
    const float* Wk_coef  = (const float*)d_in[8];
    const float* bk       = (const float*)d_in[9];
    const float* Wv_basis = (const float*)d_in[10];
    const float* Wv_coef  = (const float*)d_in[11];
    const float* bv       = (const float*)d_in[12];
    float* out = (float*)d_out;

    int E = in_sizes[1];       // 500000

    static bool attr_set = false;
    if (!attr_set) {
        cudaFuncSetAttribute(gemm_qkv_tf32, cudaFuncAttributeMaxDynamicSharedMemorySize, SMEM_TOTAL);
        attr_set = true;
    }

    // CSR build
    zero_deg<<<(MAXN + 255) / 256, 256>>>();
    hist_deg<<<(E + 255) / 256, 256>>>(dst, E);
    scan_deg<<<1, SCAN_T>>>();
    place_edges<<<(E + 255) / 256, 256>>>(src, dst, et, E);

    build_Wt<<<(NOUT * KDIM + 255) / 256, 256>>>(Wq_basis, Wq_coef, bq,
                                                 Wk_basis, Wk_coef, bk,
                                                 Wv_basis, Wv_coef, bv);

    scatter_csr<<<(MAXN * 32 + 255) / 256, 256>>>(h);

    {
        dim3 gg(NOUT / 128, NPAD / 64);
        gemm_qkv_tf32<<<gg, 256, SMEM_TOTAL>>>();
    }

    attn_csr<<<(MAXN * 32 + 255) / 256, 256>>>(out);
}

// round 8
// speedup vs baseline: 1.4011x; 1.3065x over previous
#include <cuda_runtime.h>
#include <cuda_fp16.h>
#include <cstdint>

#define D      128
#define HH     8
#define RR     6
#define BB     6
#define MAXN   50000
#define NPAD   50048              /* 782 * 64 */
#define KDIM   (RR * D)           /* 768 */
#define NOUT   (3 * D)            /* 384 */
#define MAXE   500000

// ---------------- scratch (static device globals; no allocation) ----------------
__device__ __align__(256) __half g_Sh[(size_t)NPAD * KDIM];   // fp16 per-(dst,rel) sums; rows >= MAXN stay 0
__device__ __align__(256) __half g_Wth[(size_t)NOUT * KDIM];  // [384][768] K-major W^T fp16
__device__ __align__(256) float g_bias[NOUT];
__device__ __align__(256) float g_QKV[(size_t)NPAD * NOUT];   // relu(S@W + b)
__device__ int g_deg[MAXN];
__device__ int g_rowptr[MAXN + 1];
__device__ int g_cursor[MAXN];
__device__ int g_epack[MAXE];                                 // (src<<3)|rel, sorted by dst

// ---------------- helpers ----------------
__device__ __forceinline__ uint32_t smem_u32(const void* p) {
    uint32_t a;
    asm("{ .reg .u64 t; cvta.to.shared.u64 t, %1; cvt.u32.u64 %0, t; }" : "=r"(a) : "l"(p));
    return a;
}
__device__ __forceinline__ void ldsm4(uint32_t addr, uint32_t* r) {
    asm volatile("ldmatrix.sync.aligned.m8n8.x4.shared.b16 {%0,%1,%2,%3}, [%4];"
                 : "=r"(r[0]), "=r"(r[1]), "=r"(r[2]), "=r"(r[3]) : "r"(addr));
}
__device__ __forceinline__ void mma_f16(float* c, const uint32_t* a, const uint32_t* b) {
    asm volatile("mma.sync.aligned.m16n8k16.row.col.f32.f16.f16.f32 "
                 "{%0,%1,%2,%3}, {%4,%5,%6,%7}, {%8,%9}, {%0,%1,%2,%3};"
                 : "+f"(c[0]), "+f"(c[1]), "+f"(c[2]), "+f"(c[3])
                 : "r"(a[0]), "r"(a[1]), "r"(a[2]), "r"(a[3]), "r"(b[0]), "r"(b[1]));
}

// ---------------- CSR build ----------------
__global__ void zero_deg() {
    int i = blockIdx.x * blockDim.x + threadIdx.x;
    if (i < MAXN) g_deg[i] = 0;
}
__global__ void hist_deg(const int* __restrict__ dst, int E) {
    int i = blockIdx.x * blockDim.x + threadIdx.x;
    if (i < E) atomicAdd(&g_deg[dst[i]], 1);
}
#define SCAN_T 1024
#define CHUNK  49   /* 1024*49 = 50176 >= MAXN */
__global__ void __launch_bounds__(SCAN_T) scan_deg() {
    __shared__ int sums[SCAN_T];
    int t = threadIdx.x;
    int base = t * CHUNK;
    int s = 0;
#pragma unroll 1
    for (int i = 0; i < CHUNK; i++) {
        int idx = base + i;
        if (idx < MAXN) s += g_deg[idx];
    }
    sums[t] = s;
    __syncthreads();
    for (int off = 1; off < SCAN_T; off <<= 1) {
        int v = (t >= off) ? sums[t - off] : 0;
        __syncthreads();
        if (t >= off) sums[t] += v;
        __syncthreads();
    }
    int excl = (t == 0) ? 0 : sums[t - 1];
#pragma unroll 1
    for (int i = 0; i < CHUNK; i++) {
        int idx = base + i;
        if (idx < MAXN) {
            g_rowptr[idx] = excl;
            g_cursor[idx] = excl;
            excl += g_deg[idx];
        }
    }
    if (t == SCAN_T - 1) g_rowptr[MAXN] = excl;
}
__global__ void place_edges(const int* __restrict__ src, const int* __restrict__ dst,
                            const int* __restrict__ et, int E) {
    int i = blockIdx.x * blockDim.x + threadIdx.x;
    if (i >= E) return;
    int pos = atomicAdd(&g_cursor[dst[i]], 1);
    g_epack[pos] = (src[i] << 3) | et[i];
}

// ---------------- build W^T (fp16) + bias ----------------
__global__ void build_Wt(const float* __restrict__ qb, const float* __restrict__ qc, const float* __restrict__ bq,
                         const float* __restrict__ kb, const float* __restrict__ kc, const float* __restrict__ bk,
                         const float* __restrict__ vb, const float* __restrict__ vc, const float* __restrict__ bv) {
    int idx = blockIdx.x * blockDim.x + threadIdx.x;
    if (idx < NOUT)
        g_bias[idx] = (idx < D) ? bq[idx] : (idx < 2 * D) ? bk[idx - D] : bv[idx - 2 * D];
    if (idx >= NOUT * KDIM) return;
    int o = idx / KDIM;
    int k = idx - o * KDIM;
    int r = k >> 7, i2 = k & 127;
    const float* basis; const float* coef; int oo = o;
    if (o < D)          { basis = qb; coef = qc; }
    else if (o < 2 * D) { basis = kb; coef = kc; oo = o - D; }
    else                { basis = vb; coef = vc; oo = o - 2 * D; }
    float acc = 0.f;
#pragma unroll
    for (int b = 0; b < BB; b++)
        acc += coef[r * BB + b] * basis[(size_t)b * D * D + (size_t)i2 * D + oo];
    g_Wth[idx] = __float2half_rn(acc);
}

// ---------------- scatter via CSR: warp per dst, register accum, fp16 stores ----------------
__global__ void scatter_csr(const float* __restrict__ h) {
    int d = blockIdx.x * (blockDim.x >> 5) + (threadIdx.x >> 5);
    if (d >= MAXN) return;
    int lane = threadIdx.x & 31;
    int e0 = __ldg(g_rowptr + d), e1 = __ldg(g_rowptr + d + 1);
    float4 a0 = {0,0,0,0}, a1 = {0,0,0,0}, a2 = {0,0,0,0},
           a3 = {0,0,0,0}, a4 = {0,0,0,0}, a5 = {0,0,0,0};
#pragma unroll 1
    for (int e = e0; e < e1; e++) {
        int pk = __ldg(g_epack + e);
        int src = pk >> 3, rel = pk & 7;
        float4 v = __ldg((const float4*)(h + (size_t)src * D) + lane);
        switch (rel) {
            case 0: a0.x += v.x; a0.y += v.y; a0.z += v.z; a0.w += v.w; break;
            case 1: a1.x += v.x; a1.y += v.y; a1.z += v.z; a1.w += v.w; break;
            case 2: a2.x += v.x; a2.y += v.y; a2.z += v.z; a2.w += v.w; break;
            case 3: a3.x += v.x; a3.y += v.y; a3.z += v.z; a3.w += v.w; break;
            case 4: a4.x += v.x; a4.y += v.y; a4.z += v.z; a4.w += v.w; break;
            default: a5.x += v.x; a5.y += v.y; a5.z += v.z; a5.w += v.w; break;
        }
    }
    __half2* srow = (__half2*)(g_Sh + (size_t)d * KDIM);
    srow[(0 * 128 >> 1) + lane * 2]     = __float22half2_rn(make_float2(a0.x, a0.y));
    srow[(0 * 128 >> 1) + lane * 2 + 1] = __float22half2_rn(make_float2(a0.z, a0.w));
    srow[(1 * 128 >> 1) + lane * 2]     = __float22half2_rn(make_float2(a1.x, a1.y));
    srow[(1 * 128 >> 1) + lane * 2 + 1] = __float22half2_rn(make_float2(a1.z, a1.w));
    srow[(2 * 128 >> 1) + lane * 2]     = __float22half2_rn(make_float2(a2.x, a2.y));
    srow[(2 * 128 >> 1) + lane * 2 + 1] = __float22half2_rn(make_float2(a2.z, a2.w));
    srow[(3 * 128 >> 1) + lane * 2]     = __float22half2_rn(make_float2(a3.x, a3.y));
    srow[(3 * 128 >> 1) + lane * 2 + 1] = __float22half2_rn(make_float2(a3.z, a3.w));
    srow[(4 * 128 >> 1) + lane * 2]     = __float22half2_rn(make_float2(a4.x, a4.y));
    srow[(4 * 128 >> 1) + lane * 2 + 1] = __float22half2_rn(make_float2(a4.z, a4.w));
    srow[(5 * 128 >> 1) + lane * 2]     = __float22half2_rn(make_float2(a5.x, a5.y));
    srow[(5 * 128 >> 1) + lane * 2 + 1] = __float22half2_rn(make_float2(a5.z, a5.w));
}

// ---------------- fp16 mma.sync GEMM: QKV = relu(S @ W + b) ----------------
// CTA 64(M) x 128(N), 8 warps (2M x 4N of 32x32), K-chunk 64 fp16 (128B rows,
// 8-chunk XOR swizzle), 3-stage cp.async, 72 KB smem -> 2 CTAs/SM.
#define KCH        64
#define NCHUNK     (KDIM / KCH)           /* 12 */
#define ATILEB     (64 * 128)              /* 8192 */
#define BTILEB     (128 * 128)             /* 16384 */
#define STAGEB     (ATILEB + BTILEB)       /* 24576 */
#define NSTAGE     3
#define SMEM_TOTAL (NSTAGE * STAGEB)       /* 73728 */

__device__ __forceinline__ void load_tileA(uint32_t sdst, const __half* __restrict__ g,
                                           int k0, int t) {
    // 64 rows x 128B = 512 granules of 16B, 2 per thread
#pragma unroll
    for (int i = 0; i < 2; i++) {
        int u = i * 256 + t;
        int row = u >> 3, c = u & 7;
        uint32_t off = (uint32_t)(row * 128 + ((c ^ (row & 7)) * 16));
        const void* src = g + (size_t)row * KDIM + k0 + c * 8;
        asm volatile("cp.async.cg.shared.global [%0], [%1], 16;"
                     :: "r"(sdst + off), "l"(src) : "memory");
    }
}
__device__ __forceinline__ void load_tileB(uint32_t sdst, const __half* __restrict__ g,
                                           int k0, int t) {
    // 128 rows x 128B = 1024 granules, 4 per thread
#pragma unroll
    for (int i = 0; i < 4; i++) {
        int u = i * 256 + t;
        int row = u >> 3, c = u & 7;
        uint32_t off = (uint32_t)(row * 128 + ((c ^ (row & 7)) * 16));
        const void* src = g + (size_t)row * KDIM + k0 + c * 8;
        asm volatile("cp.async.cg.shared.global [%0], [%1], 16;"
                     :: "r"(sdst + off), "l"(src) : "memory");
    }
}

__global__ void __launch_bounds__(256, 2) gemm_qkv_f16() {
    extern __shared__ char smem[];
    uint32_t sbase = smem_u32(smem);
    int t = threadIdx.x;
    int l = t & 31;
    int w = t >> 5;           // 0..7
    int wm = w & 1;           // M warp 0..1 (32 rows)
    int wn = w >> 1;          // N warp 0..3 (32 cols)
    int bm = blockIdx.y * 64;
    int bn = blockIdx.x * 128;

    const __half* A = g_Sh + (size_t)bm * KDIM;
    const __half* B = g_Wth + (size_t)bn * KDIM;

    float acc[2][4][4];
#pragma unroll
    for (int i = 0; i < 2; i++)
#pragma unroll
        for (int j = 0; j < 4; j++)
#pragma unroll
            for (int k = 0; k < 4; k++) acc[i][j][k] = 0.f;

#pragma unroll
    for (int c = 0; c < NSTAGE; c++) {
        uint32_t sb = sbase + c * STAGEB;
        load_tileA(sb,          A, c * KCH, t);
        load_tileB(sb + ATILEB, B, c * KCH, t);
        asm volatile("cp.async.commit_group;" ::: "memory");
    }

#pragma unroll 1
    for (int c = 0; c < NCHUNK; c++) {
        if (c < NCHUNK - 2)       asm volatile("cp.async.wait_group 2;" ::: "memory");
        else if (c == NCHUNK - 2) asm volatile("cp.async.wait_group 1;" ::: "memory");
        else                      asm volatile("cp.async.wait_group 0;" ::: "memory");
        __syncthreads();

        uint32_t sb = sbase + (c % NSTAGE) * STAGEB;
        uint32_t stA = sb;
        uint32_t stB = sb + ATILEB;

        // 4 k16 steps per 64-wide chunk
#pragma unroll
        for (int kk = 0; kk < 4; kk++) {
            uint32_t af[2][4], bf[4][2];
#pragma unroll
            for (int mt = 0; mt < 2; mt++) {
                uint32_t off = (uint32_t)((wm * 32 + mt * 16 + (l & 15)) * 128 +
                                          (((kk * 2 + (l >> 4)) ^ (l & 7)) * 16));
                ldsm4(stA + off, af[mt]);
            }
#pragma unroll
            for (int np = 0; np < 2; np++) {
                uint32_t off = (uint32_t)((wn * 32 + np * 16 + (l & 7) + ((l >> 4) & 1) * 8) * 128 +
                                          (((kk * 2 + ((l >> 3) & 1)) ^ (l & 7)) * 16));
                uint32_t r[4];
                ldsm4(stB + off, r);
                bf[np * 2][0] = r[0];     bf[np * 2][1] = r[1];
                bf[np * 2 + 1][0] = r[2]; bf[np * 2 + 1][1] = r[3];
            }
#pragma unroll
            for (int mt = 0; mt < 2; mt++)
#pragma unroll
                for (int nt = 0; nt < 4; nt++)
                    mma_f16(acc[mt][nt], af[mt], bf[nt]);
        }
        __syncthreads();
        if (c + NSTAGE < NCHUNK) {
            int cn = c + NSTAGE;
            load_tileA(sb,          A, cn * KCH, t);
            load_tileB(sb + ATILEB, B, cn * KCH, t);
            asm volatile("cp.async.commit_group;" ::: "memory");
        }
    }

    // epilogue: bias + relu (rows padded to NPAD, no bounds checks)
#pragma unroll
    for (int mt = 0; mt < 2; mt++) {
        int r0 = bm + wm * 32 + mt * 16 + (l >> 2);
#pragma unroll
        for (int nt = 0; nt < 4; nt++) {
            int col = bn + wn * 32 + nt * 8 + 2 * (l & 3);
            float2 bb = *(const float2*)(g_bias + col);
            float2 o0, o1;
            o0.x = fmaxf(acc[mt][nt][0] + bb.x, 0.f);
            o0.y = fmaxf(acc[mt][nt][1] + bb.y, 0.f);
            o1.x = fmaxf(acc[mt][nt][2] + bb.x, 0.f);
            o1.y = fmaxf(acc[mt][nt][3] + bb.y, 0.f);
            *(float2*)(g_QKV + (size_t)r0 * NOUT + col) = o0;
            *(float2*)(g_QKV + (size_t)(r0 + 8) * NOUT + col) = o1;
        }
    }
}

// ---------------- attention via CSR: warp per dst, no atomics, direct output ----------------
__global__ void attn_csr(float* __restrict__ out) {
    int d = blockIdx.x * (blockDim.x >> 5) + (threadIdx.x >> 5);
    if (d >= MAXN) return;
    int lane = threadIdx.x & 31;
    int e0 = __ldg(g_rowptr + d), e1 = __ldg(g_rowptr + d + 1);
    float4 q = __ldg((const float4*)(g_QKV + (size_t)d * NOUT) + lane);
    float4 wv = {0, 0, 0, 0};
    float z = 0.f;
#pragma unroll 1
    for (int e = e0; e < e1; e++) {
        int src = __ldg(g_epack + e) >> 3;
        float4 k = __ldg((const float4*)(g_QKV + (size_t)src * NOUT + D) + lane);
        float4 v = __ldg((const float4*)(g_QKV + (size_t)src * NOUT + 2 * D) + lane);
        float p = q.x * k.x + q.y * k.y + q.z * k.z + q.w * k.w;
        p += __shfl_xor_sync(0xffffffffu, p, 1);
        p += __shfl_xor_sync(0xffffffffu, p, 2);
        float w = __expf(fminf(fmaxf(p * 0.25f, -10.f), 10.f));
        wv.x += v.x * w; wv.y += v.y * w; wv.z += v.z * w; wv.w += v.w * w;
        z += w;
    }
    float inv = 1.f / (z + 1e-6f);
    float4 o = {wv.x * inv, wv.y * inv, wv.z * inv, wv.w * inv};
    *((float4*)(out + (size_t)d * D) + lane) = o;
}

extern "C" void kernel_launch(void* const* d_in, const int* in_sizes, int n_in,
                              void* d_out, int out_size) {
    const float* h   = (const float*)d_in[0];
    const int*   src = (const int*)d_in[1];
    const int*   dst = (const int*)d_in[2];
    const int*   et  = (const int*)d_in[3];
    const float* Wq_basis = (const float*)d_in[4];
    const float* Wq_coef  = (const float*)d_in[5];
    const float* bq       = (const float*)d_in[6];
    const float* Wk_basis = (const float*)d_in[7];
    const float* Wk_coef  = (const float*)d_in[8];
    const float* bk       = (const float*)d_in[9];
    const float* Wv_basis = (const float*)d_in[10];
    const float* Wv_coef  = (const float*)d_in[11];
    const float* bv       = (const float*)d_in[12];
    float* out = (float*)d_out;

    int E = in_sizes[1];       // 500000

    static bool attr_set = false;
    if (!attr_set) {
        cudaFuncSetAttribute(gemm_qkv_f16, cudaFuncAttributeMaxDynamicSharedMemorySize, SMEM_TOTAL);
        attr_set = true;
    }

    // CSR build
    zero_deg<<<(MAXN + 255) / 256, 256>>>();
    hist_deg<<<(E + 255) / 256, 256>>>(dst, E);
    scan_deg<<<1, SCAN_T>>>();
    place_edges<<<(E + 255) / 256, 256>>>(src, dst, et, E);

    build_Wt<<<(NOUT * KDIM + 255) / 256, 256>>>(Wq_basis, Wq_coef, bq,
                                                 Wk_basis, Wk_coef, bk,
                                                 Wv_basis, Wv_coef, bv);

    scatter_csr<<<(MAXN * 32 + 255) / 256, 256>>>(h);

    {
        dim3 gg(NOUT / 128, NPAD / 64);
        gemm_qkv_f16<<<gg, 256, SMEM_TOTAL>>>();
    }

    attn_csr<<<(MAXN * 32 + 255) / 256, 256>>>(out);
}